// round 2
// baseline (speedup 1.0000x reference)
#include <cuda_runtime.h>
#include <float.h>

// ---------------- problem constants ----------------
#define NB    4
#define NSEQ  4096
#define DIMX  1024
#define HEADS 16
#define DHEAD 64
#define MAG   128            // number of agent tokens
#define BHN   (NB * HEADS)   // 64
#define SCALE 0.125f         // 64^-0.5

// ---------------- scratch (device globals; no allocation) ----------------
__device__ float g_q[NB * HEADS * NSEQ * DHEAD];        // [b,h,n,d] 16.7M
__device__ float g_k[NB * HEADS * NSEQ * DHEAD];
__device__ float g_v[NB * HEADS * NSEQ * DHEAD];
__device__ float g_qa[NB * HEADS * NSEQ * MAG];         // [b,h,n,m] 33.5M
__device__ float g_ak[NB * HEADS * MAG * NSEQ];         // [b,h,m,n] 33.5M
__device__ float g_agent_part[8 * BHN * MAG * DHEAD];   // split-K partials
__device__ float g_agent[BHN * MAG * DHEAD];            // [b,h,m,d]
__device__ float g_mid[NB * NSEQ * DIMX];               // [b,n,h*d]
__device__ float g_maskf[NB * NSEQ];                    // 0/1 float mask

// ---------------- helpers ----------------
__device__ __forceinline__ float warp_max(float v) {
#pragma unroll
    for (int o = 16; o > 0; o >>= 1) v = fmaxf(v, __shfl_xor_sync(0xffffffffu, v, o));
    return v;
}
__device__ __forceinline__ float warp_sum(float v) {
#pragma unroll
    for (int o = 16; o > 0; o >>= 1) v += __shfl_xor_sync(0xffffffffu, v, o);
    return v;
}

// ---------------- mask dtype detection + expansion ----------------
// mask has 16384 elements; dtype could be bool(1B), int32, or float32.
// Inspect first 16384 bytes: float32 has bytes like 0x80/0x3f -> "weird";
// int32 has nonzero bytes only at i%4==0; bool has nonzero bytes anywhere.
__global__ void mask_expand_kernel(const void* __restrict__ mraw) {
    __shared__ int s_weird, s_off;
    const unsigned char* mb = (const unsigned char*)mraw;
    if (threadIdx.x == 0) { s_weird = 0; s_off = 0; }
    __syncthreads();
    int weird = 0, off = 0;
    for (int i = threadIdx.x; i < NB * NSEQ; i += blockDim.x) {
        unsigned char c = mb[i];
        if (c > 1) weird = 1;
        if (c != 0 && (i & 3)) off = 1;
    }
    if (weird) atomicOr(&s_weird, 1);
    if (off)   atomicOr(&s_off, 1);
    __syncthreads();
    int mode = s_weird ? 2 : (s_off ? 0 : 1);   // 0=bool/int8, 1=int32, 2=float32
    for (int i = threadIdx.x; i < NB * NSEQ; i += blockDim.x) {
        float v;
        if (mode == 0)      v = mb[i] ? 1.f : 0.f;
        else if (mode == 1) v = ((const int*)mraw)[i] ? 1.f : 0.f;
        else                v = (((const float*)mraw)[i] != 0.f) ? 1.f : 0.f;
        g_maskf[i] = v;
    }
}

// ---------------- big SGEMM: qkv projection with scatter epilogue ----------------
// C[16384 x 3072] = X[16384 x 1024] @ W[1024 x 3072], scattered to g_q/g_k/g_v [b,h,n,d]
__global__ __launch_bounds__(256) void gemm_qkv_kernel(const float* __restrict__ X,
                                                       const float* __restrict__ W) {
    const int K = 1024, N = 3072;
    __shared__ float As[16][128];
    __shared__ float Bs[16][128];
    const int tid = threadIdx.x;
    const int bm = blockIdx.y * 128;
    const int bn = blockIdx.x * 128;
    const int tx = tid & 15, ty = tid >> 4;
    const int arow = tid >> 2, akv = (tid & 3) << 2;
    const int brow = tid >> 5, bcol = (tid & 31) << 2;
    float acc[8][8] = {};
    for (int k0 = 0; k0 < K; k0 += 16) {
#pragma unroll
        for (int s = 0; s < 2; s++) {
            int r = arow + s * 64;
            float4 a4 = *reinterpret_cast<const float4*>(&X[(bm + r) * K + k0 + akv]);
            As[akv + 0][r] = a4.x; As[akv + 1][r] = a4.y;
            As[akv + 2][r] = a4.z; As[akv + 3][r] = a4.w;
        }
#pragma unroll
        for (int s = 0; s < 2; s++) {
            int kk = brow + s * 8;
            *reinterpret_cast<float4*>(&Bs[kk][bcol]) =
                *reinterpret_cast<const float4*>(&W[(k0 + kk) * N + bn + bcol]);
        }
        __syncthreads();
#pragma unroll
        for (int kk = 0; kk < 16; kk++) {
            float ra[8], rb[8];
#pragma unroll
            for (int i = 0; i < 8; i++) ra[i] = As[kk][ty * 8 + i];
#pragma unroll
            for (int j = 0; j < 8; j++) rb[j] = Bs[kk][tx * 8 + j];
#pragma unroll
            for (int i = 0; i < 8; i++)
#pragma unroll
                for (int j = 0; j < 8; j++) acc[i][j] = fmaf(ra[i], rb[j], acc[i][j]);
        }
        __syncthreads();
    }
    const int c0 = bn + tx * 8;          // 8 consecutive cols, within one 64-block
    const int which = c0 >> 10;
    const int hh = (c0 >> 6) & 15;
    const int dd = c0 & 63;
    float* dst = which == 0 ? g_q : (which == 1 ? g_k : g_v);
#pragma unroll
    for (int i = 0; i < 8; i++) {
        int r = bm + ty * 8 + i;
        int b = r >> 12, n = r & 4095;
        float* p = &dst[(((b * 16 + hh) * 4096) + n) * 64 + dd];
        *reinterpret_cast<float4*>(p)     = make_float4(acc[i][0], acc[i][1], acc[i][2], acc[i][3]);
        *reinterpret_cast<float4*>(p + 4) = make_float4(acc[i][4], acc[i][5], acc[i][6], acc[i][7]);
    }
}

// ---------------- final SGEMM: out = g_mid[16384x1024] @ W_out[1024x1024] ----------------
__global__ __launch_bounds__(256) void gemm_final_kernel(const float* __restrict__ W,
                                                         float* __restrict__ out) {
    const int K = 1024, N = 1024;
    __shared__ float As[16][128];
    __shared__ float Bs[16][128];
    const int tid = threadIdx.x;
    const int bm = blockIdx.y * 128;
    const int bn = blockIdx.x * 128;
    const int tx = tid & 15, ty = tid >> 4;
    const int arow = tid >> 2, akv = (tid & 3) << 2;
    const int brow = tid >> 5, bcol = (tid & 31) << 2;
    float acc[8][8] = {};
    for (int k0 = 0; k0 < K; k0 += 16) {
#pragma unroll
        for (int s = 0; s < 2; s++) {
            int r = arow + s * 64;
            float4 a4 = *reinterpret_cast<const float4*>(&g_mid[(bm + r) * K + k0 + akv]);
            As[akv + 0][r] = a4.x; As[akv + 1][r] = a4.y;
            As[akv + 2][r] = a4.z; As[akv + 3][r] = a4.w;
        }
#pragma unroll
        for (int s = 0; s < 2; s++) {
            int kk = brow + s * 8;
            *reinterpret_cast<float4*>(&Bs[kk][bcol]) =
                *reinterpret_cast<const float4*>(&W[(k0 + kk) * N + bn + bcol]);
        }
        __syncthreads();
#pragma unroll
        for (int kk = 0; kk < 16; kk++) {
            float ra[8], rb[8];
#pragma unroll
            for (int i = 0; i < 8; i++) ra[i] = As[kk][ty * 8 + i];
#pragma unroll
            for (int j = 0; j < 8; j++) rb[j] = Bs[kk][tx * 8 + j];
#pragma unroll
            for (int i = 0; i < 8; i++)
#pragma unroll
                for (int j = 0; j < 8; j++) acc[i][j] = fmaf(ra[i], rb[j], acc[i][j]);
        }
        __syncthreads();
    }
#pragma unroll
    for (int i = 0; i < 8; i++) {
        int r = bm + ty * 8 + i;
        float* p = &out[(size_t)r * N + bn + tx * 8];
        *reinterpret_cast<float4*>(p)     = make_float4(acc[i][0], acc[i][1], acc[i][2], acc[i][3]);
        *reinterpret_cast<float4*>(p + 4) = make_float4(acc[i][4], acc[i][5], acc[i][6], acc[i][7]);
    }
}

// ---------------- qa_sim: per (b,h): q[4096x64] @ (SCALE*a[h])^T[64x128] -> g_qa ----------------
__global__ __launch_bounds__(256) void qa_sim_kernel(const float* __restrict__ Agt) {
    __shared__ float As[16][128];
    __shared__ float Bs[16][128];
    const int tid = threadIdx.x;
    const int bh = blockIdx.y;
    const int h = bh & 15;
    const int bm = blockIdx.x * 128;
    const float* Q = g_q + bh * (NSEQ * DHEAD);
    const float* A = Agt + h * (MAG * DHEAD);
    const int tx = tid & 15, ty = tid >> 4;
    const int row = tid >> 2, kv = (tid & 3) << 2;
    float acc[8][8] = {};
    for (int k0 = 0; k0 < 64; k0 += 16) {
#pragma unroll
        for (int s = 0; s < 2; s++) {
            int r = row + s * 64;
            float4 a4 = *reinterpret_cast<const float4*>(&Q[(bm + r) * 64 + k0 + kv]);
            As[kv + 0][r] = a4.x; As[kv + 1][r] = a4.y;
            As[kv + 2][r] = a4.z; As[kv + 3][r] = a4.w;
            float4 b4 = *reinterpret_cast<const float4*>(&A[r * 64 + k0 + kv]);
            Bs[kv + 0][r] = b4.x * SCALE; Bs[kv + 1][r] = b4.y * SCALE;
            Bs[kv + 2][r] = b4.z * SCALE; Bs[kv + 3][r] = b4.w * SCALE;
        }
        __syncthreads();
#pragma unroll
        for (int kk = 0; kk < 16; kk++) {
            float ra[8], rb[8];
#pragma unroll
            for (int i = 0; i < 8; i++) ra[i] = As[kk][ty * 8 + i];
#pragma unroll
            for (int j = 0; j < 8; j++) rb[j] = Bs[kk][tx * 8 + j];
#pragma unroll
            for (int i = 0; i < 8; i++)
#pragma unroll
                for (int j = 0; j < 8; j++) acc[i][j] = fmaf(ra[i], rb[j], acc[i][j]);
        }
        __syncthreads();
    }
#pragma unroll
    for (int i = 0; i < 8; i++) {
        int ii = bm + ty * 8 + i;
        float* p = &g_qa[((size_t)bh * NSEQ + ii) * MAG + tx * 8];
        *reinterpret_cast<float4*>(p)     = make_float4(acc[i][0], acc[i][1], acc[i][2], acc[i][3]);
        *reinterpret_cast<float4*>(p + 4) = make_float4(acc[i][4], acc[i][5], acc[i][6], acc[i][7]);
    }
}

// ---------------- ak_sim: per (b,h): (SCALE*a[h])[128x64] @ k^T[64x4096] + mask -> g_ak ----------------
__global__ __launch_bounds__(256) void ak_sim_kernel(const float* __restrict__ Agt) {
    __shared__ float As[16][128];
    __shared__ float Bs[16][128];
    const int tid = threadIdx.x;
    const int bh = blockIdx.y;
    const int b = bh >> 4, h = bh & 15;
    const int bn = blockIdx.x * 128;
    const float* A  = Agt + h * (MAG * DHEAD);       // rows m, K=64
    const float* Kt = g_k + bh * (NSEQ * DHEAD);     // rows n, K=64
    const int tx = tid & 15, ty = tid >> 4;
    const int row = tid >> 2, kv = (tid & 3) << 2;
    float acc[8][8] = {};
    for (int k0 = 0; k0 < 64; k0 += 16) {
#pragma unroll
        for (int s = 0; s < 2; s++) {
            int r = row + s * 64;
            float4 a4 = *reinterpret_cast<const float4*>(&A[r * 64 + k0 + kv]);
            As[kv + 0][r] = a4.x * SCALE; As[kv + 1][r] = a4.y * SCALE;
            As[kv + 2][r] = a4.z * SCALE; As[kv + 3][r] = a4.w * SCALE;
            float4 b4 = *reinterpret_cast<const float4*>(&Kt[(bn + r) * 64 + k0 + kv]);
            Bs[kv + 0][r] = b4.x; Bs[kv + 1][r] = b4.y;
            Bs[kv + 2][r] = b4.z; Bs[kv + 3][r] = b4.w;
        }
        __syncthreads();
#pragma unroll
        for (int kk = 0; kk < 16; kk++) {
            float ra[8], rb[8];
#pragma unroll
            for (int i = 0; i < 8; i++) ra[i] = As[kk][ty * 8 + i];
#pragma unroll
            for (int j = 0; j < 8; j++) rb[j] = Bs[kk][tx * 8 + j];
#pragma unroll
            for (int i = 0; i < 8; i++)
#pragma unroll
                for (int j = 0; j < 8; j++) acc[i][j] = fmaf(ra[i], rb[j], acc[i][j]);
        }
        __syncthreads();
    }
#pragma unroll
    for (int i = 0; i < 8; i++) {
        int m = ty * 8 + i;
        float* p = &g_ak[((size_t)bh * MAG + m) * NSEQ + bn + tx * 8];
#pragma unroll
        for (int j = 0; j < 8; j++) {
            int n = bn + tx * 8 + j;
            float mv = g_maskf[b * NSEQ + n];
            p[j] = (mv != 0.f) ? acc[i][j] : -FLT_MAX;
        }
    }
}

// ---------------- softmax over m=128 (qa), one warp per row ----------------
__global__ __launch_bounds__(256) void softmax_qa_kernel() {
    int row  = blockIdx.x * 8 + (threadIdx.x >> 5);
    int lane = threadIdx.x & 31;
    float4* p = reinterpret_cast<float4*>(&g_qa[(size_t)row * MAG + lane * 4]);
    float4 v = *p;
    float mx = warp_max(fmaxf(fmaxf(v.x, v.y), fmaxf(v.z, v.w)));
    v.x = __expf(v.x - mx); v.y = __expf(v.y - mx);
    v.z = __expf(v.z - mx); v.w = __expf(v.w - mx);
    float s = warp_sum(v.x + v.y + v.z + v.w);
    float inv = 1.f / s;
    v.x *= inv; v.y *= inv; v.z *= inv; v.w *= inv;
    *p = v;
}

// ---------------- softmax over n=4096 (ak), one block per row ----------------
__global__ __launch_bounds__(256) void softmax_ak_kernel() {
    const int tid = blockIdx.x; // unused alias guard
    const int row = blockIdx.x;
    const int t = threadIdx.x;
    float* p = g_ak + (size_t)row * NSEQ;
    float4 v[4];
    float mx = -FLT_MAX;
#pragma unroll
    for (int i = 0; i < 4; i++) {
        v[i] = *reinterpret_cast<float4*>(&p[t * 16 + i * 4]);
        mx = fmaxf(mx, fmaxf(fmaxf(v[i].x, v[i].y), fmaxf(v[i].z, v[i].w)));
    }
    __shared__ float red[8];
    int wid = t >> 5, lane = t & 31;
    float wm = warp_max(mx);
    if (lane == 0) red[wid] = wm;
    __syncthreads();
    float m = red[0];
#pragma unroll
    for (int i = 1; i < 8; i++) m = fmaxf(m, red[i]);
    float s = 0.f;
#pragma unroll
    for (int i = 0; i < 4; i++) {
        v[i].x = __expf(v[i].x - m); v[i].y = __expf(v[i].y - m);
        v[i].z = __expf(v[i].z - m); v[i].w = __expf(v[i].w - m);
        s += v[i].x + v[i].y + v[i].z + v[i].w;
    }
    float ws = warp_sum(s);
    __syncthreads();
    if (lane == 0) red[wid] = ws;
    __syncthreads();
    float tot = 0.f;
#pragma unroll
    for (int i = 0; i < 8; i++) tot += red[i];
    float inv = 1.f / tot;
#pragma unroll
    for (int i = 0; i < 4; i++) {
        v[i].x *= inv; v[i].y *= inv; v[i].z *= inv; v[i].w *= inv;
        *reinterpret_cast<float4*>(&p[t * 16 + i * 4]) = v[i];
    }
    (void)tid;
}

// ---------------- talking heads: in-place 16x16 head mix ----------------
// layout [b][h][R] with R = inner size; out[g] = sum_h W[g,h]*x[h]
__global__ __launch_bounds__(256) void mix_heads_kernel(int which, const float* __restrict__ Wm) {
    __shared__ float Ws[256];
    if (threadIdx.x < 256) Ws[threadIdx.x] = Wm[threadIdx.x];
    __syncthreads();
    float* base = which ? g_ak : g_qa;
    const size_t R = (size_t)NSEQ * MAG;   // 524288 (same for both layouts)
    size_t pos = (size_t)blockIdx.x * blockDim.x + threadIdx.x;
    if (pos >= (size_t)NB * R) return;
    size_t b = pos / R, r = pos % R;
    float* p = base + b * 16 * R + r;
    float x[16];
#pragma unroll
    for (int h = 0; h < 16; h++) x[h] = p[h * R];
#pragma unroll
    for (int g = 0; g < 16; g++) {
        float s = 0.f;
#pragma unroll
        for (int h = 0; h < 16; h++) s = fmaf(Ws[g * 16 + h], x[h], s);
        p[g * R] = s;
    }
}

// ---------------- agent_out: per (b,h): ak2[128x4096] @ v[4096x64], split-K=8 ----------------
__global__ __launch_bounds__(256) void agent_out_kernel() {
    __shared__ float As[16][128];
    __shared__ float Bs[16][64];
    const int tid = threadIdx.x;
    const int sp = blockIdx.x;       // split 0..7
    const int bh = blockIdx.y;
    const float* A = g_ak + (size_t)bh * MAG * NSEQ;   // [128, 4096]
    const float* V = g_v + (size_t)bh * NSEQ * DHEAD;  // [4096, 64]
    const int tx = tid & 15, ty = tid >> 4;
    const int arow = tid >> 2, akv = (tid & 3) << 2;
    const int bk = tid >> 4, bn4 = (tid & 15) << 2;
    float acc[8][4] = {};
    const int kend = sp * 512 + 512;
    for (int k0 = sp * 512; k0 < kend; k0 += 16) {
#pragma unroll
        for (int s = 0; s < 2; s++) {
            int r = arow + s * 64;
            float4 a4 = *reinterpret_cast<const float4*>(&A[r * 4096 + k0 + akv]);
            As[akv + 0][r] = a4.x; As[akv + 1][r] = a4.y;
            As[akv + 2][r] = a4.z; As[akv + 3][r] = a4.w;
        }
        *reinterpret_cast<float4*>(&Bs[bk][bn4]) =
            *reinterpret_cast<const float4*>(&V[(k0 + bk) * 64 + bn4]);
        __syncthreads();
#pragma unroll
        for (int kk = 0; kk < 16; kk++) {
            float ra[8], rb[4];
#pragma unroll
            for (int i = 0; i < 8; i++) ra[i] = As[kk][ty * 8 + i];
#pragma unroll
            for (int j = 0; j < 4; j++) rb[j] = Bs[kk][tx * 4 + j];
#pragma unroll
            for (int i = 0; i < 8; i++)
#pragma unroll
                for (int j = 0; j < 4; j++) acc[i][j] = fmaf(ra[i], rb[j], acc[i][j]);
        }
        __syncthreads();
    }
    float* P = g_agent_part + (size_t)sp * (BHN * MAG * DHEAD) + (size_t)bh * (MAG * DHEAD);
#pragma unroll
    for (int i = 0; i < 8; i++)
        *reinterpret_cast<float4*>(&P[(ty * 8 + i) * 64 + tx * 4]) =
            make_float4(acc[i][0], acc[i][1], acc[i][2], acc[i][3]);
}

// fixed-order split-K reduction (deterministic)
__global__ __launch_bounds__(256) void reduce_agent_kernel() {
    int i = blockIdx.x * 256 + threadIdx.x;
    float s = 0.f;
#pragma unroll
    for (int k = 0; k < 8; k++) s += g_agent_part[(size_t)k * (BHN * MAG * DHEAD) + i];
    g_agent[i] = s;
}

// ---------------- out: per (b,h): qa2[4096x128] @ agent[128x64], mask, -> g_mid [b,n,h*d] ----------------
__global__ __launch_bounds__(256) void out_mid_kernel() {
    __shared__ float As[16][128];
    __shared__ float Bs[16][64];
    const int tid = threadIdx.x;
    const int bh = blockIdx.y;
    const int b = bh >> 4, h = bh & 15;
    const int bm = blockIdx.x * 128;
    const float* A = g_qa + (size_t)bh * NSEQ * MAG;   // [4096, 128]
    const float* G = g_agent + (size_t)bh * MAG * DHEAD; // [128, 64]
    const int tx = tid & 15, ty = tid >> 4;
    const int arow = tid >> 2, akv = (tid & 3) << 2;
    const int bk = tid >> 4, bn4 = (tid & 15) << 2;
    float acc[8][4] = {};
    for (int k0 = 0; k0 < 128; k0 += 16) {
#pragma unroll
        for (int s = 0; s < 2; s++) {
            int r = arow + s * 64;
            float4 a4 = *reinterpret_cast<const float4*>(&A[(bm + r) * 128 + k0 + akv]);
            As[akv + 0][r] = a4.x; As[akv + 1][r] = a4.y;
            As[akv + 2][r] = a4.z; As[akv + 3][r] = a4.w;
        }
        *reinterpret_cast<float4*>(&Bs[bk][bn4]) =
            *reinterpret_cast<const float4*>(&G[(k0 + bk) * 64 + bn4]);
        __syncthreads();
#pragma unroll
        for (int kk = 0; kk < 16; kk++) {
            float ra[8], rb[4];
#pragma unroll
            for (int i = 0; i < 8; i++) ra[i] = As[kk][ty * 8 + i];
#pragma unroll
            for (int j = 0; j < 4; j++) rb[j] = Bs[kk][tx * 4 + j];
#pragma unroll
            for (int i = 0; i < 8; i++)
#pragma unroll
                for (int j = 0; j < 4; j++) acc[i][j] = fmaf(ra[i], rb[j], acc[i][j]);
        }
        __syncthreads();
    }
#pragma unroll
    for (int i = 0; i < 8; i++) {
        int r = bm + ty * 8 + i;                  // n index
        float mv = g_maskf[b * NSEQ + r];
        float* p = &g_mid[((size_t)b * NSEQ + r) * DIMX + h * 64 + tx * 4];
        *reinterpret_cast<float4*>(p) =
            make_float4(acc[i][0] * mv, acc[i][1] * mv, acc[i][2] * mv, acc[i][3] * mv);
    }
}

// ---------------- launcher ----------------
extern "C" void kernel_launch(void* const* d_in, const int* in_sizes, int n_in,
                              void* d_out, int out_size) {
    const float* x     = (const float*)d_in[0];
    const void*  mask  = d_in[1];
    const float* Wqkv  = (const float*)d_in[2];
    const float* agent = (const float*)d_in[3];
    const float* Wqa   = (const float*)d_in[4];
    const float* Wak   = (const float*)d_in[5];
    const float* Wout  = (const float*)d_in[6];
    float* out = (float*)d_out;
    (void)in_sizes; (void)n_in; (void)out_size;

    mask_expand_kernel<<<1, 1024>>>(mask);
    gemm_qkv_kernel<<<dim3(24, 128), 256>>>(x, Wqkv);          // 16384x3072x1024
    qa_sim_kernel<<<dim3(32, 64), 256>>>(agent);               // per (b,h) 4096x128x64
    ak_sim_kernel<<<dim3(32, 64), 256>>>(agent);               // per (b,h) 128x4096x64 + mask
    softmax_qa_kernel<<<(NB * HEADS * NSEQ) / 8, 256>>>();     // rows of 128
    softmax_ak_kernel<<<NB * HEADS * MAG, 256>>>();            // rows of 4096
    mix_heads_kernel<<<8192, 256>>>(0, Wqa);                   // in-place qa head mix
    mix_heads_kernel<<<8192, 256>>>(1, Wak);                   // in-place ak head mix
    agent_out_kernel<<<dim3(8, 64), 256>>>();                  // split-K=8
    reduce_agent_kernel<<<(BHN * MAG * DHEAD) / 256, 256>>>();
    out_mid_kernel<<<dim3(32, 64), 256>>>();                   // per (b,h) 4096x64x128 + mask
    gemm_final_kernel<<<dim3(8, 128), 256>>>(Wout, out);       // 16384x1024x1024
}

// round 4
// speedup vs baseline: 1.9479x; 1.9479x over previous
#include <cuda_runtime.h>
#include <cuda_bf16.h>
#include <stdint.h>
#include <float.h>

// ---------------- problem constants ----------------
#define NB    4
#define NSEQ  4096
#define DIMX  1024
#define HEADS 16
#define DHEAD 64
#define MAG   128
#define BHN   (NB * HEADS)
#define SCALE 0.125f

// ---------------- scratch (device globals; no allocation) ----------------
__device__ float g_q[NB * HEADS * NSEQ * DHEAD];
__device__ float g_k[NB * HEADS * NSEQ * DHEAD];
__device__ float g_v[NB * HEADS * NSEQ * DHEAD];
__device__ float g_qa[NB * HEADS * NSEQ * MAG];
__device__ float g_ak[NB * HEADS * MAG * NSEQ];
__device__ float g_agent_part[8 * BHN * MAG * DHEAD];
__device__ float g_agent[BHN * MAG * DHEAD];
__device__ float g_maskf[NB * NSEQ];

// bf16 split operands for tensor-core GEMMs
__device__ __nv_bfloat16 g_xh[NB * NSEQ * DIMX];       // X hi  [16384,1024]
__device__ __nv_bfloat16 g_xl[NB * NSEQ * DIMX];       // X lo
__device__ __nv_bfloat16 g_wqkvh[3 * DIMX * DIMX];     // Wqkv^T hi [3072,1024]
__device__ __nv_bfloat16 g_wqkvl[3 * DIMX * DIMX];
__device__ __nv_bfloat16 g_wouth[DIMX * DIMX];         // Wout^T hi [1024,1024]
__device__ __nv_bfloat16 g_woutl[DIMX * DIMX];
__device__ __nv_bfloat16 g_midh[NB * NSEQ * DIMX];     // mid hi [16384,1024]
__device__ __nv_bfloat16 g_midl[NB * NSEQ * DIMX];

// ---------------- PTX helpers (base sm_103 only; NO tcgen05) ----------------
__device__ __forceinline__ uint32_t smem_u32(const void* p) {
    uint32_t a;
    asm("{ .reg .u64 t; cvta.to.shared.u64 t, %1; cvt.u32.u64 %0, t; }" : "=r"(a) : "l"(p));
    return a;
}
#define SMEM_SWIZZLE_128B(o) ((o) ^ (((o) >> 3) & 0x70))

__device__ __forceinline__ void cp_async16(uint32_t sa, const void* g) {
    asm volatile("cp.async.cg.shared.global [%0], [%1], 16;" :: "r"(sa), "l"(g));
}
#define CP_COMMIT() asm volatile("cp.async.commit_group;" ::: "memory")
#define CP_WAIT(n)  asm volatile("cp.async.wait_group %0;" :: "n"(n) : "memory")

__device__ __forceinline__ void ldsm_x4(uint32_t* r, uint32_t a) {
    asm volatile("ldmatrix.sync.aligned.m8n8.x4.shared.b16 {%0,%1,%2,%3}, [%4];"
                 : "=r"(r[0]), "=r"(r[1]), "=r"(r[2]), "=r"(r[3]) : "r"(a));
}
__device__ __forceinline__ void mma16816(float* c, const uint32_t* a, const uint32_t* b) {
    asm volatile("mma.sync.aligned.m16n8k16.row.col.f32.bf16.bf16.f32 "
                 "{%0,%1,%2,%3}, {%4,%5,%6,%7}, {%8,%9}, {%0,%1,%2,%3};"
                 : "+f"(c[0]), "+f"(c[1]), "+f"(c[2]), "+f"(c[3])
                 : "r"(a[0]), "r"(a[1]), "r"(a[2]), "r"(a[3]), "r"(b[0]), "r"(b[1]));
}

// ---------------- generic helpers ----------------
__device__ __forceinline__ float warp_max(float v) {
#pragma unroll
    for (int o = 16; o > 0; o >>= 1) v = fmaxf(v, __shfl_xor_sync(0xffffffffu, v, o));
    return v;
}
__device__ __forceinline__ float warp_sum(float v) {
#pragma unroll
    for (int o = 16; o > 0; o >>= 1) v += __shfl_xor_sync(0xffffffffu, v, o);
    return v;
}
__device__ __forceinline__ void split_hl(float v, __nv_bfloat16& h, __nv_bfloat16& l) {
    h = __float2bfloat16(v);
    l = __float2bfloat16(v - __bfloat162float(h));
}

// ---------------- mask dtype detection + expansion ----------------
__global__ void mask_expand_kernel(const void* __restrict__ mraw) {
    __shared__ int s_weird, s_off;
    const unsigned char* mb = (const unsigned char*)mraw;
    if (threadIdx.x == 0) { s_weird = 0; s_off = 0; }
    __syncthreads();
    int weird = 0, off = 0;
    for (int i = threadIdx.x; i < NB * NSEQ; i += blockDim.x) {
        unsigned char c = mb[i];
        if (c > 1) weird = 1;
        if (c != 0 && (i & 3)) off = 1;
    }
    if (weird) atomicOr(&s_weird, 1);
    if (off)   atomicOr(&s_off, 1);
    __syncthreads();
    int mode = s_weird ? 2 : (s_off ? 0 : 1);
    for (int i = threadIdx.x; i < NB * NSEQ; i += blockDim.x) {
        float v;
        if (mode == 0)      v = mb[i] ? 1.f : 0.f;
        else if (mode == 1) v = ((const int*)mraw)[i] ? 1.f : 0.f;
        else                v = (((const float*)mraw)[i] != 0.f) ? 1.f : 0.f;
        g_maskf[i] = v;
    }
}

// ---------------- fp32 -> bf16 hi/lo split ----------------
__global__ __launch_bounds__(256) void conv_split_kernel(const float* __restrict__ src,
                                                         __nv_bfloat16* __restrict__ h,
                                                         __nv_bfloat16* __restrict__ l, int n4) {
    int i = blockIdx.x * 256 + threadIdx.x;
    if (i >= n4) return;
    float4 v = reinterpret_cast<const float4*>(src)[i];
    __nv_bfloat16 h0, h1, h2, h3, l0, l1, l2, l3;
    split_hl(v.x, h0, l0); split_hl(v.y, h1, l1);
    split_hl(v.z, h2, l2); split_hl(v.w, h3, l3);
    reinterpret_cast<__nv_bfloat162*>(h)[i * 2]     = __nv_bfloat162(h0, h1);
    reinterpret_cast<__nv_bfloat162*>(h)[i * 2 + 1] = __nv_bfloat162(h2, h3);
    reinterpret_cast<__nv_bfloat162*>(l)[i * 2]     = __nv_bfloat162(l0, l1);
    reinterpret_cast<__nv_bfloat162*>(l)[i * 2 + 1] = __nv_bfloat162(l2, l3);
}

// ---------------- W[K,N] -> W^T[N,K] bf16 hi/lo ----------------
__global__ __launch_bounds__(256) void conv_wt_kernel(const float* __restrict__ W,
                                                      __nv_bfloat16* __restrict__ Th,
                                                      __nv_bfloat16* __restrict__ Tl,
                                                      int K, int N) {
    __shared__ float t[32][33];
    int bx = blockIdx.x * 32;  // n
    int by = blockIdx.y * 32;  // k
    int x = threadIdx.x & 31, y0 = threadIdx.x >> 5;
#pragma unroll
    for (int y = y0; y < 32; y += 8) t[y][x] = W[(size_t)(by + y) * N + bx + x];
    __syncthreads();
#pragma unroll
    for (int y = y0; y < 32; y += 8) {
        float v = t[x][y];
        __nv_bfloat16 h, l;
        split_hl(v, h, l);
        size_t o = (size_t)(bx + y) * K + by + x;
        Th[o] = h; Tl[o] = l;
    }
}

// ---------------- mma.sync bf16x3 GEMM: C[M,N] = A[M,K] @ B[N,K]^T ----------------
// CTA 128x128 tile, BK=64 halves, SW128-swizzled smem, double-buffered cp.async.
// 8 warps: warp grid 2(m) x 4(n); warp tile 64x32; m16n8k16 frags.
// MODE 0: fp32 store to out[row*Nout+col].  MODE 1: scatter to g_q/g_k/g_v.
#define GT_TILE  16384                 // 128 rows x 128 bytes
#define GT_STAGE (4 * GT_TILE)         // Ah, Al, Bh, Bl
#define GT_SMEM  (1024 + 2 * GT_STAGE) // align pad + 2 stages = 132096

template <int MODE>
__global__ __launch_bounds__(256, 1) void gemm_mma_kernel(
    const __nv_bfloat16* __restrict__ Ah, const __nv_bfloat16* __restrict__ Al,
    const __nv_bfloat16* __restrict__ Bh, const __nv_bfloat16* __restrict__ Bl,
    float* __restrict__ out, int Kdim, int Nout) {
    extern __shared__ char dsm[];
    uint32_t sraw = smem_u32(dsm);
    uint32_t sbase = (sraw + 1023u) & ~1023u;

    const int tid = threadIdx.x;
    const int lane = tid & 31;
    const int wid = tid >> 5;
    const int wm = wid >> 2;           // 0..1
    const int wn = wid & 3;            // 0..3
    const int bm = blockIdx.y * 128;
    const int bn = blockIdx.x * 128;

    float acc[4][4][4];
#pragma unroll
    for (int i = 0; i < 4; i++)
#pragma unroll
        for (int j = 0; j < 4; j++)
#pragma unroll
            for (int v = 0; v < 4; v++) acc[i][j][v] = 0.f;

    const int nchunk = Kdim >> 6;      // BK = 64

    // per-thread load coordinates: 4 x 16B per tile
    const int lr  = tid >> 3;          // 0..31 base row (stride 32)
    const int lc  = (tid & 7) << 4;    // byte col 0..112

    auto load_chunk = [&](int c) {
        const int buf = c & 1;
        const int k0 = c << 6;
        const uint32_t sb = sbase + buf * GT_STAGE;
#pragma unroll
        for (int i = 0; i < 4; i++) {
            int r = lr + i * 32;
            uint32_t so = SMEM_SWIZZLE_128B(r * 128 + lc);
            size_t go = (size_t)(bm + r) * Kdim + k0 + (lc >> 1);
            size_t gb = (size_t)(bn + r) * Kdim + k0 + (lc >> 1);
            cp_async16(sb + 0 * GT_TILE + so, Ah + go);
            cp_async16(sb + 1 * GT_TILE + so, Al + go);
            cp_async16(sb + 2 * GT_TILE + so, Bh + gb);
            cp_async16(sb + 3 * GT_TILE + so, Bl + gb);
        }
        CP_COMMIT();
    };

    load_chunk(0);
    if (nchunk > 1) load_chunk(1);

    const int lrow = lane & 15;
    const int lksel = (lane >> 4) << 4;   // 0 or 16 bytes (k half)

    for (int c = 0; c < nchunk; c++) {
        if (c + 1 < nchunk) { CP_WAIT(1); } else { CP_WAIT(0); }
        __syncthreads();
        const uint32_t sb = sbase + (c & 1) * GT_STAGE;
        const uint32_t a_h = sb, a_l = sb + GT_TILE;
        const uint32_t b_h = sb + 2 * GT_TILE, b_l = sb + 3 * GT_TILE;
#pragma unroll
        for (int ks = 0; ks < 4; ks++) {
            const int kb = ks * 32 + lksel;   // byte offset of this k16 step
            uint32_t ah[4][4], al[4][4], bh[4][2], bl[4][2];
#pragma unroll
            for (int mf = 0; mf < 4; mf++) {
                int row = wm * 64 + mf * 16 + lrow;
                uint32_t so = SMEM_SWIZZLE_128B(row * 128 + kb);
                ldsm_x4(ah[mf], a_h + so);
                ldsm_x4(al[mf], a_l + so);
            }
#pragma unroll
            for (int g = 0; g < 2; g++) {
                int row = wn * 32 + g * 16 + lrow;
                uint32_t so = SMEM_SWIZZLE_128B(row * 128 + kb);
                uint32_t r[4];
                ldsm_x4(r, b_h + so);
                bh[g * 2][0] = r[0]; bh[g * 2][1] = r[2];
                bh[g * 2 + 1][0] = r[1]; bh[g * 2 + 1][1] = r[3];
                ldsm_x4(r, b_l + so);
                bl[g * 2][0] = r[0]; bl[g * 2][1] = r[2];
                bl[g * 2 + 1][0] = r[1]; bl[g * 2 + 1][1] = r[3];
            }
#pragma unroll
            for (int mf = 0; mf < 4; mf++)
#pragma unroll
                for (int nf = 0; nf < 4; nf++) mma16816(acc[mf][nf], ah[mf], bh[nf]);
#pragma unroll
            for (int mf = 0; mf < 4; mf++)
#pragma unroll
                for (int nf = 0; nf < 4; nf++) mma16816(acc[mf][nf], ah[mf], bl[nf]);
#pragma unroll
            for (int mf = 0; mf < 4; mf++)
#pragma unroll
                for (int nf = 0; nf < 4; nf++) mma16816(acc[mf][nf], al[mf], bh[nf]);
        }
        __syncthreads();
        if (c + 2 < nchunk) load_chunk(c + 2);
    }

    // ---------------- epilogue ----------------
#pragma unroll
    for (int mf = 0; mf < 4; mf++) {
        int r0 = bm + wm * 64 + mf * 16 + (lane >> 2);
#pragma unroll
        for (int nf = 0; nf < 4; nf++) {
            int col = bn + wn * 32 + nf * 8 + ((lane & 3) << 1);
            float* p0;
            float* p1;
            if (MODE == 1) {
                const int which = col >> 10;
                const int hh = (col >> 6) & 15;
                const int d0 = col & 63;
                float* dst = which == 0 ? g_q : (which == 1 ? g_k : g_v);
                const int b0 = r0 >> 12, n0 = r0 & 4095;
                const int b1 = (r0 + 8) >> 12, n1 = (r0 + 8) & 4095;
                p0 = &dst[(((size_t)(b0 * 16 + hh)) * 4096 + n0) * 64 + d0];
                p1 = &dst[(((size_t)(b1 * 16 + hh)) * 4096 + n1) * 64 + d0];
            } else {
                p0 = &out[(size_t)r0 * Nout + col];
                p1 = &out[(size_t)(r0 + 8) * Nout + col];
            }
            *reinterpret_cast<float2*>(p0) = make_float2(acc[mf][nf][0], acc[mf][nf][1]);
            *reinterpret_cast<float2*>(p1) = make_float2(acc[mf][nf][2], acc[mf][nf][3]);
        }
    }
}

// ---------------- qa_sim: per (b,h): q[4096x64] @ (SCALE*a[h])^T[64x128] ----------------
__global__ __launch_bounds__(256) void qa_sim_kernel(const float* __restrict__ Agt) {
    __shared__ float As[16][128];
    __shared__ float Bs[16][128];
    const int tid = threadIdx.x;
    const int bh = blockIdx.y;
    const int h = bh & 15;
    const int bm = blockIdx.x * 128;
    const float* Q = g_q + bh * (NSEQ * DHEAD);
    const float* A = Agt + h * (MAG * DHEAD);
    const int tx = tid & 15, ty = tid >> 4;
    const int row = tid >> 2, kv = (tid & 3) << 2;
    float acc[8][8] = {};
    for (int k0 = 0; k0 < 64; k0 += 16) {
#pragma unroll
        for (int s = 0; s < 2; s++) {
            int r = row + s * 64;
            float4 a4 = *reinterpret_cast<const float4*>(&Q[(bm + r) * 64 + k0 + kv]);
            As[kv + 0][r] = a4.x; As[kv + 1][r] = a4.y;
            As[kv + 2][r] = a4.z; As[kv + 3][r] = a4.w;
            float4 b4 = *reinterpret_cast<const float4*>(&A[r * 64 + k0 + kv]);
            Bs[kv + 0][r] = b4.x * SCALE; Bs[kv + 1][r] = b4.y * SCALE;
            Bs[kv + 2][r] = b4.z * SCALE; Bs[kv + 3][r] = b4.w * SCALE;
        }
        __syncthreads();
#pragma unroll
        for (int kk = 0; kk < 16; kk++) {
            float ra[8], rb[8];
#pragma unroll
            for (int i = 0; i < 8; i++) ra[i] = As[kk][ty * 8 + i];
#pragma unroll
            for (int j = 0; j < 8; j++) rb[j] = Bs[kk][tx * 8 + j];
#pragma unroll
            for (int i = 0; i < 8; i++)
#pragma unroll
                for (int j = 0; j < 8; j++) acc[i][j] = fmaf(ra[i], rb[j], acc[i][j]);
        }
        __syncthreads();
    }
#pragma unroll
    for (int i = 0; i < 8; i++) {
        int ii = bm + ty * 8 + i;
        float* p = &g_qa[((size_t)bh * NSEQ + ii) * MAG + tx * 8];
        *reinterpret_cast<float4*>(p)     = make_float4(acc[i][0], acc[i][1], acc[i][2], acc[i][3]);
        *reinterpret_cast<float4*>(p + 4) = make_float4(acc[i][4], acc[i][5], acc[i][6], acc[i][7]);
    }
}

// ---------------- ak_sim ----------------
__global__ __launch_bounds__(256) void ak_sim_kernel(const float* __restrict__ Agt) {
    __shared__ float As[16][128];
    __shared__ float Bs[16][128];
    const int tid = threadIdx.x;
    const int bh = blockIdx.y;
    const int b = bh >> 4, h = bh & 15;
    const int bn = blockIdx.x * 128;
    const float* A  = Agt + h * (MAG * DHEAD);
    const float* Kt = g_k + bh * (NSEQ * DHEAD);
    const int tx = tid & 15, ty = tid >> 4;
    const int row = tid >> 2, kv = (tid & 3) << 2;
    float acc[8][8] = {};
    for (int k0 = 0; k0 < 64; k0 += 16) {
#pragma unroll
        for (int s = 0; s < 2; s++) {
            int r = row + s * 64;
            float4 a4 = *reinterpret_cast<const float4*>(&A[r * 64 + k0 + kv]);
            As[kv + 0][r] = a4.x * SCALE; As[kv + 1][r] = a4.y * SCALE;
            As[kv + 2][r] = a4.z * SCALE; As[kv + 3][r] = a4.w * SCALE;
            float4 b4 = *reinterpret_cast<const float4*>(&Kt[(bn + r) * 64 + k0 + kv]);
            Bs[kv + 0][r] = b4.x; Bs[kv + 1][r] = b4.y;
            Bs[kv + 2][r] = b4.z; Bs[kv + 3][r] = b4.w;
        }
        __syncthreads();
#pragma unroll
        for (int kk = 0; kk < 16; kk++) {
            float ra[8], rb[8];
#pragma unroll
            for (int i = 0; i < 8; i++) ra[i] = As[kk][ty * 8 + i];
#pragma unroll
            for (int j = 0; j < 8; j++) rb[j] = Bs[kk][tx * 8 + j];
#pragma unroll
            for (int i = 0; i < 8; i++)
#pragma unroll
                for (int j = 0; j < 8; j++) acc[i][j] = fmaf(ra[i], rb[j], acc[i][j]);
        }
        __syncthreads();
    }
#pragma unroll
    for (int i = 0; i < 8; i++) {
        int m = ty * 8 + i;
        float* p = &g_ak[((size_t)bh * MAG + m) * NSEQ + bn + tx * 8];
#pragma unroll
        for (int j = 0; j < 8; j++) {
            int n = bn + tx * 8 + j;
            float mv = g_maskf[b * NSEQ + n];
            p[j] = (mv != 0.f) ? acc[i][j] : -FLT_MAX;
        }
    }
}

// ---------------- softmaxes ----------------
__global__ __launch_bounds__(256) void softmax_qa_kernel() {
    int row  = blockIdx.x * 8 + (threadIdx.x >> 5);
    int lane = threadIdx.x & 31;
    float4* p = reinterpret_cast<float4*>(&g_qa[(size_t)row * MAG + lane * 4]);
    float4 v = *p;
    float mx = warp_max(fmaxf(fmaxf(v.x, v.y), fmaxf(v.z, v.w)));
    v.x = __expf(v.x - mx); v.y = __expf(v.y - mx);
    v.z = __expf(v.z - mx); v.w = __expf(v.w - mx);
    float s = warp_sum(v.x + v.y + v.z + v.w);
    float inv = 1.f / s;
    v.x *= inv; v.y *= inv; v.z *= inv; v.w *= inv;
    *p = v;
}

__global__ __launch_bounds__(256) void softmax_ak_kernel() {
    const int row = blockIdx.x;
    const int t = threadIdx.x;
    float* p = g_ak + (size_t)row * NSEQ;
    float4 v[4];
    float mx = -FLT_MAX;
#pragma unroll
    for (int i = 0; i < 4; i++) {
        v[i] = *reinterpret_cast<float4*>(&p[t * 16 + i * 4]);
        mx = fmaxf(mx, fmaxf(fmaxf(v[i].x, v[i].y), fmaxf(v[i].z, v[i].w)));
    }
    __shared__ float red[8];
    int wid = t >> 5, lane = t & 31;
    float wm = warp_max(mx);
    if (lane == 0) red[wid] = wm;
    __syncthreads();
    float m = red[0];
#pragma unroll
    for (int i = 1; i < 8; i++) m = fmaxf(m, red[i]);
    float s = 0.f;
#pragma unroll
    for (int i = 0; i < 4; i++) {
        v[i].x = __expf(v[i].x - m); v[i].y = __expf(v[i].y - m);
        v[i].z = __expf(v[i].z - m); v[i].w = __expf(v[i].w - m);
        s += v[i].x + v[i].y + v[i].z + v[i].w;
    }
    float ws = warp_sum(s);
    __syncthreads();
    if (lane == 0) red[wid] = ws;
    __syncthreads();
    float tot = 0.f;
#pragma unroll
    for (int i = 0; i < 8; i++) tot += red[i];
    float inv = 1.f / tot;
#pragma unroll
    for (int i = 0; i < 4; i++) {
        v[i].x *= inv; v[i].y *= inv; v[i].z *= inv; v[i].w *= inv;
        *reinterpret_cast<float4*>(&p[t * 16 + i * 4]) = v[i];
    }
}

// ---------------- talking heads ----------------
__global__ __launch_bounds__(256) void mix_heads_kernel(int which, const float* __restrict__ Wm) {
    __shared__ float Ws[256];
    if (threadIdx.x < 256) Ws[threadIdx.x] = Wm[threadIdx.x];
    __syncthreads();
    float* base = which ? g_ak : g_qa;
    const size_t R = (size_t)NSEQ * MAG;
    size_t pos = (size_t)blockIdx.x * blockDim.x + threadIdx.x;
    if (pos >= (size_t)NB * R) return;
    size_t b = pos / R, r = pos % R;
    float* p = base + b * 16 * R + r;
    float x[16];
#pragma unroll
    for (int h = 0; h < 16; h++) x[h] = p[h * R];
#pragma unroll
    for (int g = 0; g < 16; g++) {
        float s = 0.f;
#pragma unroll
        for (int h = 0; h < 16; h++) s = fmaf(Ws[g * 16 + h], x[h], s);
        p[g * R] = s;
    }
}

// ---------------- agent_out (split-K=8) ----------------
__global__ __launch_bounds__(256) void agent_out_kernel() {
    __shared__ float As[16][128];
    __shared__ float Bs[16][64];
    const int tid = threadIdx.x;
    const int sp = blockIdx.x;
    const int bh = blockIdx.y;
    const float* A = g_ak + (size_t)bh * MAG * NSEQ;
    const float* V = g_v + (size_t)bh * NSEQ * DHEAD;
    const int tx = tid & 15, ty = tid >> 4;
    const int arow = tid >> 2, akv = (tid & 3) << 2;
    const int bk = tid >> 4, bn4 = (tid & 15) << 2;
    float acc[8][4] = {};
    const int kend = sp * 512 + 512;
    for (int k0 = sp * 512; k0 < kend; k0 += 16) {
#pragma unroll
        for (int s = 0; s < 2; s++) {
            int r = arow + s * 64;
            float4 a4 = *reinterpret_cast<const float4*>(&A[r * 4096 + k0 + akv]);
            As[akv + 0][r] = a4.x; As[akv + 1][r] = a4.y;
            As[akv + 2][r] = a4.z; As[akv + 3][r] = a4.w;
        }
        *reinterpret_cast<float4*>(&Bs[bk][bn4]) =
            *reinterpret_cast<const float4*>(&V[(k0 + bk) * 64 + bn4]);
        __syncthreads();
#pragma unroll
        for (int kk = 0; kk < 16; kk++) {
            float ra[8], rb[4];
#pragma unroll
            for (int i = 0; i < 8; i++) ra[i] = As[kk][ty * 8 + i];
#pragma unroll
            for (int j = 0; j < 4; j++) rb[j] = Bs[kk][tx * 4 + j];
#pragma unroll
            for (int i = 0; i < 8; i++)
#pragma unroll
                for (int j = 0; j < 4; j++) acc[i][j] = fmaf(ra[i], rb[j], acc[i][j]);
        }
        __syncthreads();
    }
    float* P = g_agent_part + (size_t)sp * (BHN * MAG * DHEAD) + (size_t)bh * (MAG * DHEAD);
#pragma unroll
    for (int i = 0; i < 8; i++)
        *reinterpret_cast<float4*>(&P[(ty * 8 + i) * 64 + tx * 4]) =
            make_float4(acc[i][0], acc[i][1], acc[i][2], acc[i][3]);
}

__global__ __launch_bounds__(256) void reduce_agent_kernel() {
    int i = blockIdx.x * 256 + threadIdx.x;
    float s = 0.f;
#pragma unroll
    for (int k = 0; k < 8; k++) s += g_agent_part[(size_t)k * (BHN * MAG * DHEAD) + i];
    g_agent[i] = s;
}

// ---------------- out_mid: qa2 @ agent, mask, emit bf16 hi/lo mid ----------------
__global__ __launch_bounds__(256) void out_mid_kernel() {
    __shared__ float As[16][128];
    __shared__ float Bs[16][64];
    const int tid = threadIdx.x;
    const int bh = blockIdx.y;
    const int b = bh >> 4, h = bh & 15;
    const int bm = blockIdx.x * 128;
    const float* A = g_qa + (size_t)bh * NSEQ * MAG;
    const float* G = g_agent + (size_t)bh * MAG * DHEAD;
    const int tx = tid & 15, ty = tid >> 4;
    const int arow = tid >> 2, akv = (tid & 3) << 2;
    const int bk = tid >> 4, bn4 = (tid & 15) << 2;
    float acc[8][4] = {};
    for (int k0 = 0; k0 < 128; k0 += 16) {
#pragma unroll
        for (int s = 0; s < 2; s++) {
            int r = arow + s * 64;
            float4 a4 = *reinterpret_cast<const float4*>(&A[(bm + r) * 128 + k0 + akv]);
            As[akv + 0][r] = a4.x; As[akv + 1][r] = a4.y;
            As[akv + 2][r] = a4.z; As[akv + 3][r] = a4.w;
        }
        *reinterpret_cast<float4*>(&Bs[bk][bn4]) =
            *reinterpret_cast<const float4*>(&G[(k0 + bk) * 64 + bn4]);
        __syncthreads();
#pragma unroll
        for (int kk = 0; kk < 16; kk++) {
            float ra[8], rb[4];
#pragma unroll
            for (int i = 0; i < 8; i++) ra[i] = As[kk][ty * 8 + i];
#pragma unroll
            for (int j = 0; j < 4; j++) rb[j] = Bs[kk][tx * 4 + j];
#pragma unroll
            for (int i = 0; i < 8; i++)
#pragma unroll
                for (int j = 0; j < 4; j++) acc[i][j] = fmaf(ra[i], rb[j], acc[i][j]);
        }
        __syncthreads();
    }
#pragma unroll
    for (int i = 0; i < 8; i++) {
        int r = bm + ty * 8 + i;
        float mv = g_maskf[b * NSEQ + r];
        size_t o = ((size_t)b * NSEQ + r) * DIMX + h * 64 + tx * 4;
        __nv_bfloat16 hh0, ll0, hh1, ll1, hh2, ll2, hh3, ll3;
        split_hl(acc[i][0] * mv, hh0, ll0);
        split_hl(acc[i][1] * mv, hh1, ll1);
        split_hl(acc[i][2] * mv, hh2, ll2);
        split_hl(acc[i][3] * mv, hh3, ll3);
        reinterpret_cast<__nv_bfloat162*>(&g_midh[o])[0] = __nv_bfloat162(hh0, hh1);
        reinterpret_cast<__nv_bfloat162*>(&g_midh[o])[1] = __nv_bfloat162(hh2, hh3);
        reinterpret_cast<__nv_bfloat162*>(&g_midl[o])[0] = __nv_bfloat162(ll0, ll1);
        reinterpret_cast<__nv_bfloat162*>(&g_midl[o])[1] = __nv_bfloat162(ll2, ll3);
    }
}

// ---------------- launcher ----------------
extern "C" void kernel_launch(void* const* d_in, const int* in_sizes, int n_in,
                              void* d_out, int out_size) {
    const float* x     = (const float*)d_in[0];
    const void*  mask  = d_in[1];
    const float* Wqkv  = (const float*)d_in[2];
    const float* agent = (const float*)d_in[3];
    const float* Wqa   = (const float*)d_in[4];
    const float* Wak   = (const float*)d_in[5];
    const float* Wout  = (const float*)d_in[6];
    float* out = (float*)d_out;
    (void)in_sizes; (void)n_in; (void)out_size;

    cudaFuncSetAttribute(gemm_mma_kernel<0>, cudaFuncAttributeMaxDynamicSharedMemorySize, GT_SMEM);
    cudaFuncSetAttribute(gemm_mma_kernel<1>, cudaFuncAttributeMaxDynamicSharedMemorySize, GT_SMEM);

    __nv_bfloat16 *xh, *xl, *wqh, *wql, *woh, *wol, *mh, *ml;
    cudaGetSymbolAddress((void**)&xh,  g_xh);
    cudaGetSymbolAddress((void**)&xl,  g_xl);
    cudaGetSymbolAddress((void**)&wqh, g_wqkvh);
    cudaGetSymbolAddress((void**)&wql, g_wqkvl);
    cudaGetSymbolAddress((void**)&woh, g_wouth);
    cudaGetSymbolAddress((void**)&wol, g_woutl);
    cudaGetSymbolAddress((void**)&mh,  g_midh);
    cudaGetSymbolAddress((void**)&ml,  g_midl);

    mask_expand_kernel<<<1, 1024>>>(mask);
    conv_split_kernel<<<(NB * NSEQ * DIMX / 4 + 255) / 256, 256>>>(x, xh, xl, NB * NSEQ * DIMX / 4);
    conv_wt_kernel<<<dim3(96, 32), 256>>>(Wqkv, wqh, wql, 1024, 3072);
    conv_wt_kernel<<<dim3(32, 32), 256>>>(Wout, woh, wol, 1024, 1024);

    gemm_mma_kernel<1><<<dim3(24, 128), 256, GT_SMEM>>>(xh, xl, wqh, wql, nullptr, 1024, 3072);

    qa_sim_kernel<<<dim3(32, 64), 256>>>(agent);
    ak_sim_kernel<<<dim3(32, 64), 256>>>(agent);
    softmax_qa_kernel<<<(NB * HEADS * NSEQ) / 8, 256>>>();
    softmax_ak_kernel<<<NB * HEADS * MAG, 256>>>();
    mix_heads_kernel<<<8192, 256>>>(0, Wqa);
    mix_heads_kernel<<<8192, 256>>>(1, Wak);
    agent_out_kernel<<<dim3(8, 64), 256>>>();
    reduce_agent_kernel<<<(BHN * MAG * DHEAD) / 256, 256>>>();
    out_mid_kernel<<<dim3(32, 64), 256>>>();

    gemm_mma_kernel<0><<<dim3(8, 128), 256, GT_SMEM>>>(mh, ml, woh, wol, out, 1024, 1024);
}

// round 5
// speedup vs baseline: 2.0314x; 1.0429x over previous
#include <cuda_runtime.h>
#include <cuda_bf16.h>
#include <stdint.h>
#include <float.h>

// ---------------- problem constants ----------------
#define NB    4
#define NSEQ  4096
#define DIMX  1024
#define HEADS 16
#define DHEAD 64
#define MAG   128
#define BHN   (NB * HEADS)
#define SCALE 0.125f

// ---------------- scratch (device globals; no allocation) ----------------
__device__ float g_q[NB * HEADS * NSEQ * DHEAD];
__device__ float g_k[NB * HEADS * NSEQ * DHEAD];
__device__ float g_v[NB * HEADS * NSEQ * DHEAD];
__device__ float g_qa[NB * HEADS * NSEQ * MAG];
__device__ float g_ak[NB * HEADS * MAG * NSEQ];
__device__ float g_agent_part[8 * BHN * MAG * DHEAD];
__device__ float g_agent[BHN * MAG * DHEAD];
__device__ float g_maskf[NB * NSEQ];
__device__ float2 g_akstat[BHN * MAG];                 // (max, 1/sumexp) per ak row

// bf16 split operands for tensor-core GEMMs
__device__ __nv_bfloat16 g_xh[NB * NSEQ * DIMX];
__device__ __nv_bfloat16 g_xl[NB * NSEQ * DIMX];
__device__ __nv_bfloat16 g_wqkvh[3 * DIMX * DIMX];
__device__ __nv_bfloat16 g_wqkvl[3 * DIMX * DIMX];
__device__ __nv_bfloat16 g_wouth[DIMX * DIMX];
__device__ __nv_bfloat16 g_woutl[DIMX * DIMX];
__device__ __nv_bfloat16 g_midh[NB * NSEQ * DIMX];
__device__ __nv_bfloat16 g_midl[NB * NSEQ * DIMX];

// ---------------- PTX helpers (base sm_103 only; NO tcgen05) ----------------
__device__ __forceinline__ uint32_t smem_u32(const void* p) {
    uint32_t a;
    asm("{ .reg .u64 t; cvta.to.shared.u64 t, %1; cvt.u32.u64 %0, t; }" : "=r"(a) : "l"(p));
    return a;
}
#define SMEM_SWIZZLE_128B(o) ((o) ^ (((o) >> 3) & 0x70))

__device__ __forceinline__ void cp_async16(uint32_t sa, const void* g) {
    asm volatile("cp.async.cg.shared.global [%0], [%1], 16;" :: "r"(sa), "l"(g));
}
#define CP_COMMIT() asm volatile("cp.async.commit_group;" ::: "memory")
#define CP_WAIT(n)  asm volatile("cp.async.wait_group %0;" :: "n"(n) : "memory")

__device__ __forceinline__ void ldsm_x4(uint32_t* r, uint32_t a) {
    asm volatile("ldmatrix.sync.aligned.m8n8.x4.shared.b16 {%0,%1,%2,%3}, [%4];"
                 : "=r"(r[0]), "=r"(r[1]), "=r"(r[2]), "=r"(r[3]) : "r"(a));
}
__device__ __forceinline__ void mma16816(float* c, const uint32_t* a, const uint32_t* b) {
    asm volatile("mma.sync.aligned.m16n8k16.row.col.f32.bf16.bf16.f32 "
                 "{%0,%1,%2,%3}, {%4,%5,%6,%7}, {%8,%9}, {%0,%1,%2,%3};"
                 : "+f"(c[0]), "+f"(c[1]), "+f"(c[2]), "+f"(c[3])
                 : "r"(a[0]), "r"(a[1]), "r"(a[2]), "r"(a[3]), "r"(b[0]), "r"(b[1]));
}

// ---------------- generic helpers ----------------
__device__ __forceinline__ float warp_max(float v) {
#pragma unroll
    for (int o = 16; o > 0; o >>= 1) v = fmaxf(v, __shfl_xor_sync(0xffffffffu, v, o));
    return v;
}
__device__ __forceinline__ float warp_sum(float v) {
#pragma unroll
    for (int o = 16; o > 0; o >>= 1) v += __shfl_xor_sync(0xffffffffu, v, o);
    return v;
}
__device__ __forceinline__ void split_hl(float v, __nv_bfloat16& h, __nv_bfloat16& l) {
    h = __float2bfloat16(v);
    l = __float2bfloat16(v - __bfloat162float(h));
}

// ---------------- mask dtype detection + expansion ----------------
__global__ void mask_expand_kernel(const void* __restrict__ mraw) {
    __shared__ int s_weird, s_off;
    const unsigned char* mb = (const unsigned char*)mraw;
    if (threadIdx.x == 0) { s_weird = 0; s_off = 0; }
    __syncthreads();
    int weird = 0, off = 0;
    for (int i = threadIdx.x; i < NB * NSEQ; i += blockDim.x) {
        unsigned char c = mb[i];
        if (c > 1) weird = 1;
        if (c != 0 && (i & 3)) off = 1;
    }
    if (weird) atomicOr(&s_weird, 1);
    if (off)   atomicOr(&s_off, 1);
    __syncthreads();
    int mode = s_weird ? 2 : (s_off ? 0 : 1);
    for (int i = threadIdx.x; i < NB * NSEQ; i += blockDim.x) {
        float v;
        if (mode == 0)      v = mb[i] ? 1.f : 0.f;
        else if (mode == 1) v = ((const int*)mraw)[i] ? 1.f : 0.f;
        else                v = (((const float*)mraw)[i] != 0.f) ? 1.f : 0.f;
        g_maskf[i] = v;
    }
}

// ---------------- fp32 -> bf16 hi/lo split ----------------
__global__ __launch_bounds__(256) void conv_split_kernel(const float* __restrict__ src,
                                                         __nv_bfloat16* __restrict__ h,
                                                         __nv_bfloat16* __restrict__ l, int n4) {
    int i = blockIdx.x * 256 + threadIdx.x;
    if (i >= n4) return;
    float4 v = reinterpret_cast<const float4*>(src)[i];
    __nv_bfloat16 h0, h1, h2, h3, l0, l1, l2, l3;
    split_hl(v.x, h0, l0); split_hl(v.y, h1, l1);
    split_hl(v.z, h2, l2); split_hl(v.w, h3, l3);
    reinterpret_cast<__nv_bfloat162*>(h)[i * 2]     = __nv_bfloat162(h0, h1);
    reinterpret_cast<__nv_bfloat162*>(h)[i * 2 + 1] = __nv_bfloat162(h2, h3);
    reinterpret_cast<__nv_bfloat162*>(l)[i * 2]     = __nv_bfloat162(l0, l1);
    reinterpret_cast<__nv_bfloat162*>(l)[i * 2 + 1] = __nv_bfloat162(l2, l3);
}

// ---------------- W[K,N] -> W^T[N,K] bf16 hi/lo ----------------
__global__ __launch_bounds__(256) void conv_wt_kernel(const float* __restrict__ W,
                                                      __nv_bfloat16* __restrict__ Th,
                                                      __nv_bfloat16* __restrict__ Tl,
                                                      int K, int N) {
    __shared__ float t[32][33];
    int bx = blockIdx.x * 32;
    int by = blockIdx.y * 32;
    int x = threadIdx.x & 31, y0 = threadIdx.x >> 5;
#pragma unroll
    for (int y = y0; y < 32; y += 8) t[y][x] = W[(size_t)(by + y) * N + bx + x];
    __syncthreads();
#pragma unroll
    for (int y = y0; y < 32; y += 8) {
        float v = t[x][y];
        __nv_bfloat16 h, l;
        split_hl(v, h, l);
        size_t o = (size_t)(bx + y) * K + by + x;
        Th[o] = h; Tl[o] = l;
    }
}

// ---------------- mma.sync bf16x3 GEMM (unchanged from R3 pass) ----------------
#define GT_TILE  16384
#define GT_STAGE (4 * GT_TILE)
#define GT_SMEM  (1024 + 2 * GT_STAGE)

template <int MODE>
__global__ __launch_bounds__(256, 1) void gemm_mma_kernel(
    const __nv_bfloat16* __restrict__ Ah, const __nv_bfloat16* __restrict__ Al,
    const __nv_bfloat16* __restrict__ Bh, const __nv_bfloat16* __restrict__ Bl,
    float* __restrict__ out, int Kdim, int Nout) {
    extern __shared__ char dsm[];
    uint32_t sraw = smem_u32(dsm);
    uint32_t sbase = (sraw + 1023u) & ~1023u;

    const int tid = threadIdx.x;
    const int lane = tid & 31;
    const int wid = tid >> 5;
    const int wm = wid >> 2;
    const int wn = wid & 3;
    const int bm = blockIdx.y * 128;
    const int bn = blockIdx.x * 128;

    float acc[4][4][4];
#pragma unroll
    for (int i = 0; i < 4; i++)
#pragma unroll
        for (int j = 0; j < 4; j++)
#pragma unroll
            for (int v = 0; v < 4; v++) acc[i][j][v] = 0.f;

    const int nchunk = Kdim >> 6;
    const int lr  = tid >> 3;
    const int lc  = (tid & 7) << 4;

    auto load_chunk = [&](int c) {
        const int buf = c & 1;
        const int k0 = c << 6;
        const uint32_t sb = sbase + buf * GT_STAGE;
#pragma unroll
        for (int i = 0; i < 4; i++) {
            int r = lr + i * 32;
            uint32_t so = SMEM_SWIZZLE_128B(r * 128 + lc);
            size_t go = (size_t)(bm + r) * Kdim + k0 + (lc >> 1);
            size_t gb = (size_t)(bn + r) * Kdim + k0 + (lc >> 1);
            cp_async16(sb + 0 * GT_TILE + so, Ah + go);
            cp_async16(sb + 1 * GT_TILE + so, Al + go);
            cp_async16(sb + 2 * GT_TILE + so, Bh + gb);
            cp_async16(sb + 3 * GT_TILE + so, Bl + gb);
        }
        CP_COMMIT();
    };

    load_chunk(0);
    if (nchunk > 1) load_chunk(1);

    const int lrow = lane & 15;
    const int lksel = (lane >> 4) << 4;

    for (int c = 0; c < nchunk; c++) {
        if (c + 1 < nchunk) { CP_WAIT(1); } else { CP_WAIT(0); }
        __syncthreads();
        const uint32_t sb = sbase + (c & 1) * GT_STAGE;
        const uint32_t a_h = sb, a_l = sb + GT_TILE;
        const uint32_t b_h = sb + 2 * GT_TILE, b_l = sb + 3 * GT_TILE;
#pragma unroll
        for (int ks = 0; ks < 4; ks++) {
            const int kb = ks * 32 + lksel;
            uint32_t ah[4][4], al[4][4], bh[4][2], bl[4][2];
#pragma unroll
            for (int mf = 0; mf < 4; mf++) {
                int row = wm * 64 + mf * 16 + lrow;
                uint32_t so = SMEM_SWIZZLE_128B(row * 128 + kb);
                ldsm_x4(ah[mf], a_h + so);
                ldsm_x4(al[mf], a_l + so);
            }
#pragma unroll
            for (int g = 0; g < 2; g++) {
                int row = wn * 32 + g * 16 + lrow;
                uint32_t so = SMEM_SWIZZLE_128B(row * 128 + kb);
                uint32_t r[4];
                ldsm_x4(r, b_h + so);
                bh[g * 2][0] = r[0]; bh[g * 2][1] = r[2];
                bh[g * 2 + 1][0] = r[1]; bh[g * 2 + 1][1] = r[3];
                ldsm_x4(r, b_l + so);
                bl[g * 2][0] = r[0]; bl[g * 2][1] = r[2];
                bl[g * 2 + 1][0] = r[1]; bl[g * 2 + 1][1] = r[3];
            }
#pragma unroll
            for (int mf = 0; mf < 4; mf++)
#pragma unroll
                for (int nf = 0; nf < 4; nf++) mma16816(acc[mf][nf], ah[mf], bh[nf]);
#pragma unroll
            for (int mf = 0; mf < 4; mf++)
#pragma unroll
                for (int nf = 0; nf < 4; nf++) mma16816(acc[mf][nf], ah[mf], bl[nf]);
#pragma unroll
            for (int mf = 0; mf < 4; mf++)
#pragma unroll
                for (int nf = 0; nf < 4; nf++) mma16816(acc[mf][nf], al[mf], bh[nf]);
        }
        __syncthreads();
        if (c + 2 < nchunk) load_chunk(c + 2);
    }

#pragma unroll
    for (int mf = 0; mf < 4; mf++) {
        int r0 = bm + wm * 64 + mf * 16 + (lane >> 2);
#pragma unroll
        for (int nf = 0; nf < 4; nf++) {
            int col = bn + wn * 32 + nf * 8 + ((lane & 3) << 1);
            float* p0;
            float* p1;
            if (MODE == 1) {
                const int which = col >> 10;
                const int hh = (col >> 6) & 15;
                const int d0 = col & 63;
                float* dst = which == 0 ? g_q : (which == 1 ? g_k : g_v);
                const int b0 = r0 >> 12, n0 = r0 & 4095;
                const int b1 = (r0 + 8) >> 12, n1 = (r0 + 8) & 4095;
                p0 = &dst[(((size_t)(b0 * 16 + hh)) * 4096 + n0) * 64 + d0];
                p1 = &dst[(((size_t)(b1 * 16 + hh)) * 4096 + n1) * 64 + d0];
            } else {
                p0 = &out[(size_t)r0 * Nout + col];
                p1 = &out[(size_t)(r0 + 8) * Nout + col];
            }
            *reinterpret_cast<float2*>(p0) = make_float2(acc[mf][nf][0], acc[mf][nf][1]);
            *reinterpret_cast<float2*>(p1) = make_float2(acc[mf][nf][2], acc[mf][nf][3]);
        }
    }
}

// ---------------- qa_sim + fused softmax over m ----------------
// Block: (b,h) x n-tile(128). Whole K=64 in smem. Thread (tx,ty): rows n=ty*8+i, cols m=tx*8+j.
// Tile contains full m axis -> row softmax via 16-lane shfl groups (same-ty threads = lanes tx+(ty&1)*16).
#define SIM_SMEM (2 * 64 * 128 * 4)   // 65536
__global__ __launch_bounds__(256) void qa_sim_softmax_kernel(const float* __restrict__ Agt) {
    extern __shared__ float s[];
    float (*Qs)[128] = reinterpret_cast<float(*)[128]>(s);           // [k][row]
    float (*As)[128] = reinterpret_cast<float(*)[128]>(s + 64 * 128);
    const int tid = threadIdx.x;
    const int bh = blockIdx.y;
    const int h = bh & 15;
    const int bm = blockIdx.x * 128;
    const float* Q = g_q + (size_t)bh * (NSEQ * DHEAD);
    const float* A = Agt + (size_t)h * (MAG * DHEAD);
    const int tx = tid & 15, ty = tid >> 4;
    const int row = tid >> 2, kv = (tid & 3) << 2;
#pragma unroll
    for (int k0 = 0; k0 < 64; k0 += 16) {
#pragma unroll
        for (int s2 = 0; s2 < 2; s2++) {
            int r = row + s2 * 64;
            float4 a4 = *reinterpret_cast<const float4*>(&Q[(bm + r) * 64 + k0 + kv]);
            Qs[k0 + kv + 0][r] = a4.x; Qs[k0 + kv + 1][r] = a4.y;
            Qs[k0 + kv + 2][r] = a4.z; Qs[k0 + kv + 3][r] = a4.w;
            float4 b4 = *reinterpret_cast<const float4*>(&A[r * 64 + k0 + kv]);
            As[k0 + kv + 0][r] = b4.x * SCALE; As[k0 + kv + 1][r] = b4.y * SCALE;
            As[k0 + kv + 2][r] = b4.z * SCALE; As[k0 + kv + 3][r] = b4.w * SCALE;
        }
    }
    __syncthreads();
    float acc[8][8] = {};
#pragma unroll 8
    for (int kk = 0; kk < 64; kk++) {
        float4 ra0 = *reinterpret_cast<const float4*>(&Qs[kk][ty * 8]);
        float4 ra1 = *reinterpret_cast<const float4*>(&Qs[kk][ty * 8 + 4]);
        float4 rb0 = *reinterpret_cast<const float4*>(&As[kk][tx * 8]);
        float4 rb1 = *reinterpret_cast<const float4*>(&As[kk][tx * 8 + 4]);
        float ra[8] = {ra0.x, ra0.y, ra0.z, ra0.w, ra1.x, ra1.y, ra1.z, ra1.w};
        float rb[8] = {rb0.x, rb0.y, rb0.z, rb0.w, rb1.x, rb1.y, rb1.z, rb1.w};
#pragma unroll
        for (int i = 0; i < 8; i++)
#pragma unroll
            for (int j = 0; j < 8; j++) acc[i][j] = fmaf(ra[i], rb[j], acc[i][j]);
    }
    // fused softmax over m (cols): reduce within thread then across the 16 tx lanes
#pragma unroll
    for (int i = 0; i < 8; i++) {
        float mx = acc[i][0];
#pragma unroll
        for (int j = 1; j < 8; j++) mx = fmaxf(mx, acc[i][j]);
#pragma unroll
        for (int o = 8; o > 0; o >>= 1) mx = fmaxf(mx, __shfl_xor_sync(0xffffffffu, mx, o));
        float sm = 0.f;
#pragma unroll
        for (int j = 0; j < 8; j++) { acc[i][j] = __expf(acc[i][j] - mx); sm += acc[i][j]; }
#pragma unroll
        for (int o = 8; o > 0; o >>= 1) sm += __shfl_xor_sync(0xffffffffu, sm, o);
        float inv = 1.f / sm;
        int ii = bm + ty * 8 + i;
        float* p = &g_qa[((size_t)bh * NSEQ + ii) * MAG + tx * 8];
        *reinterpret_cast<float4*>(p) =
            make_float4(acc[i][0] * inv, acc[i][1] * inv, acc[i][2] * inv, acc[i][3] * inv);
        *reinterpret_cast<float4*>(p + 4) =
            make_float4(acc[i][4] * inv, acc[i][5] * inv, acc[i][6] * inv, acc[i][7] * inv);
    }
}

// ---------------- ak_sim: whole-K smem, mask epilogue ----------------
__global__ __launch_bounds__(256) void ak_sim_kernel(const float* __restrict__ Agt) {
    extern __shared__ float s[];
    float (*As)[128] = reinterpret_cast<float(*)[128]>(s);           // agent rows m
    float (*Ks)[128] = reinterpret_cast<float(*)[128]>(s + 64 * 128);// k rows n
    const int tid = threadIdx.x;
    const int bh = blockIdx.y;
    const int b = bh >> 4, h = bh & 15;
    const int bn = blockIdx.x * 128;
    const float* A  = Agt + (size_t)h * (MAG * DHEAD);
    const float* Kt = g_k + (size_t)bh * (NSEQ * DHEAD);
    const int tx = tid & 15, ty = tid >> 4;
    const int row = tid >> 2, kv = (tid & 3) << 2;
#pragma unroll
    for (int k0 = 0; k0 < 64; k0 += 16) {
#pragma unroll
        for (int s2 = 0; s2 < 2; s2++) {
            int r = row + s2 * 64;
            float4 a4 = *reinterpret_cast<const float4*>(&A[r * 64 + k0 + kv]);
            As[k0 + kv + 0][r] = a4.x * SCALE; As[k0 + kv + 1][r] = a4.y * SCALE;
            As[k0 + kv + 2][r] = a4.z * SCALE; As[k0 + kv + 3][r] = a4.w * SCALE;
            float4 b4 = *reinterpret_cast<const float4*>(&Kt[(bn + r) * 64 + k0 + kv]);
            Ks[k0 + kv + 0][r] = b4.x; Ks[k0 + kv + 1][r] = b4.y;
            Ks[k0 + kv + 2][r] = b4.z; Ks[k0 + kv + 3][r] = b4.w;
        }
    }
    __syncthreads();
    float acc[8][8] = {};
#pragma unroll 8
    for (int kk = 0; kk < 64; kk++) {
        float4 ra0 = *reinterpret_cast<const float4*>(&As[kk][ty * 8]);
        float4 ra1 = *reinterpret_cast<const float4*>(&As[kk][ty * 8 + 4]);
        float4 rb0 = *reinterpret_cast<const float4*>(&Ks[kk][tx * 8]);
        float4 rb1 = *reinterpret_cast<const float4*>(&Ks[kk][tx * 8 + 4]);
        float ra[8] = {ra0.x, ra0.y, ra0.z, ra0.w, ra1.x, ra1.y, ra1.z, ra1.w};
        float rb[8] = {rb0.x, rb0.y, rb0.z, rb0.w, rb1.x, rb1.y, rb1.z, rb1.w};
#pragma unroll
        for (int i = 0; i < 8; i++)
#pragma unroll
            for (int j = 0; j < 8; j++) acc[i][j] = fmaf(ra[i], rb[j], acc[i][j]);
    }
#pragma unroll
    for (int i = 0; i < 8; i++) {
        int m = ty * 8 + i;
        float* p = &g_ak[((size_t)bh * MAG + m) * NSEQ + bn + tx * 8];
#pragma unroll
        for (int j = 0; j < 8; j++) {
            int n = bn + tx * 8 + j;
            float mv = g_maskf[b * NSEQ + n];
            p[j] = (mv != 0.f) ? acc[i][j] : -FLT_MAX;
        }
    }
}

// ---------------- ak row stats: (max, 1/sumexp) over n=4096 ----------------
__global__ __launch_bounds__(256) void ak_stats_kernel() {
    const int row = blockIdx.x;
    const int t = threadIdx.x;
    const float* p = g_ak + (size_t)row * NSEQ;
    float4 v[4];
    float mx = -FLT_MAX;
#pragma unroll
    for (int i = 0; i < 4; i++) {
        v[i] = *reinterpret_cast<const float4*>(&p[t * 16 + i * 4]);
        mx = fmaxf(mx, fmaxf(fmaxf(v[i].x, v[i].y), fmaxf(v[i].z, v[i].w)));
    }
    __shared__ float red[8];
    int wid = t >> 5, lane = t & 31;
    float wm = warp_max(mx);
    if (lane == 0) red[wid] = wm;
    __syncthreads();
    float m = red[0];
#pragma unroll
    for (int i = 1; i < 8; i++) m = fmaxf(m, red[i]);
    float sacc = 0.f;
#pragma unroll
    for (int i = 0; i < 4; i++) {
        sacc += __expf(v[i].x - m) + __expf(v[i].y - m) + __expf(v[i].z - m) + __expf(v[i].w - m);
    }
    float ws = warp_sum(sacc);
    __syncthreads();
    if (lane == 0) red[wid] = ws;
    __syncthreads();
    if (t == 0) {
        float tot = 0.f;
#pragma unroll
        for (int i = 0; i < 8; i++) tot += red[i];
        g_akstat[row] = make_float2(m, 1.f / tot);
    }
}

// ---------------- fused exp-normalize + 16x16 head mix for ak (in place) ----------------
__global__ __launch_bounds__(256) void mix_ak_exp_kernel(const float* __restrict__ Wm) {
    __shared__ float Ws[256];
    if (threadIdx.x < 256) Ws[threadIdx.x] = Wm[threadIdx.x];
    __syncthreads();
    const size_t R = (size_t)MAG * NSEQ;   // 524288
    size_t pos = (size_t)blockIdx.x * blockDim.x + threadIdx.x;
    if (pos >= (size_t)NB * R) return;
    size_t b = pos / R, r = pos % R;
    int m = (int)(r >> 12);
    float* p = g_ak + b * 16 * R + r;
    float x[16];
#pragma unroll
    for (int h = 0; h < 16; h++) {
        float2 st = g_akstat[(b * 16 + h) * MAG + m];
        x[h] = __expf(p[h * R] - st.x) * st.y;
    }
#pragma unroll
    for (int g = 0; g < 16; g++) {
        float sacc = 0.f;
#pragma unroll
        for (int h = 0; h < 16; h++) sacc = fmaf(Ws[g * 16 + h], x[h], sacc);
        p[g * R] = sacc;
    }
}

// ---------------- talking heads (qa side) ----------------
__global__ __launch_bounds__(256) void mix_heads_kernel(const float* __restrict__ Wm) {
    __shared__ float Ws[256];
    if (threadIdx.x < 256) Ws[threadIdx.x] = Wm[threadIdx.x];
    __syncthreads();
    const size_t R = (size_t)NSEQ * MAG;
    size_t pos = (size_t)blockIdx.x * blockDim.x + threadIdx.x;
    if (pos >= (size_t)NB * R) return;
    size_t b = pos / R, r = pos % R;
    float* p = g_qa + b * 16 * R + r;
    float x[16];
#pragma unroll
    for (int h = 0; h < 16; h++) x[h] = p[h * R];
#pragma unroll
    for (int g = 0; g < 16; g++) {
        float sacc = 0.f;
#pragma unroll
        for (int h = 0; h < 16; h++) sacc = fmaf(Ws[g * 16 + h], x[h], sacc);
        p[g * R] = sacc;
    }
}

// ---------------- agent_out (split-K=8) ----------------
__global__ __launch_bounds__(256) void agent_out_kernel() {
    __shared__ float As[16][128];
    __shared__ float Bs[16][64];
    const int tid = threadIdx.x;
    const int sp = blockIdx.x;
    const int bh = blockIdx.y;
    const float* A = g_ak + (size_t)bh * MAG * NSEQ;
    const float* V = g_v + (size_t)bh * NSEQ * DHEAD;
    const int tx = tid & 15, ty = tid >> 4;
    const int arow = tid >> 2, akv = (tid & 3) << 2;
    const int bk = tid >> 4, bn4 = (tid & 15) << 2;
    float acc[8][4] = {};
    const int kend = sp * 512 + 512;
    for (int k0 = sp * 512; k0 < kend; k0 += 16) {
#pragma unroll
        for (int s2 = 0; s2 < 2; s2++) {
            int r = arow + s2 * 64;
            float4 a4 = *reinterpret_cast<const float4*>(&A[r * 4096 + k0 + akv]);
            As[akv + 0][r] = a4.x; As[akv + 1][r] = a4.y;
            As[akv + 2][r] = a4.z; As[akv + 3][r] = a4.w;
        }
        *reinterpret_cast<float4*>(&Bs[bk][bn4]) =
            *reinterpret_cast<const float4*>(&V[(k0 + bk) * 64 + bn4]);
        __syncthreads();
#pragma unroll
        for (int kk = 0; kk < 16; kk++) {
            float ra[8], rb[4];
#pragma unroll
            for (int i = 0; i < 8; i++) ra[i] = As[kk][ty * 8 + i];
#pragma unroll
            for (int j = 0; j < 4; j++) rb[j] = Bs[kk][tx * 4 + j];
#pragma unroll
            for (int i = 0; i < 8; i++)
#pragma unroll
                for (int j = 0; j < 4; j++) acc[i][j] = fmaf(ra[i], rb[j], acc[i][j]);
        }
        __syncthreads();
    }
    float* P = g_agent_part + (size_t)sp * (BHN * MAG * DHEAD) + (size_t)bh * (MAG * DHEAD);
#pragma unroll
    for (int i = 0; i < 8; i++)
        *reinterpret_cast<float4*>(&P[(ty * 8 + i) * 64 + tx * 4]) =
            make_float4(acc[i][0], acc[i][1], acc[i][2], acc[i][3]);
}

__global__ __launch_bounds__(256) void reduce_agent_kernel() {
    int i = blockIdx.x * 256 + threadIdx.x;
    float sacc = 0.f;
#pragma unroll
    for (int k = 0; k < 8; k++) sacc += g_agent_part[(size_t)k * (BHN * MAG * DHEAD) + i];
    g_agent[i] = sacc;
}

// ---------------- out_mid: qa2 @ agent, mask, emit bf16 hi/lo mid ----------------
__global__ __launch_bounds__(256) void out_mid_kernel() {
    __shared__ float As[16][128];
    __shared__ float Bs[16][64];
    const int tid = threadIdx.x;
    const int bh = blockIdx.y;
    const int b = bh >> 4, h = bh & 15;
    const int bm = blockIdx.x * 128;
    const float* A = g_qa + (size_t)bh * NSEQ * MAG;
    const float* G = g_agent + (size_t)bh * MAG * DHEAD;
    const int tx = tid & 15, ty = tid >> 4;
    const int arow = tid >> 2, akv = (tid & 3) << 2;
    const int bk = tid >> 4, bn4 = (tid & 15) << 2;
    float acc[8][4] = {};
    for (int k0 = 0; k0 < 128; k0 += 16) {
#pragma unroll
        for (int s2 = 0; s2 < 2; s2++) {
            int r = arow + s2 * 64;
            float4 a4 = *reinterpret_cast<const float4*>(&A[(bm + r) * 128 + k0 + akv]);
            As[akv + 0][r] = a4.x; As[akv + 1][r] = a4.y;
            As[akv + 2][r] = a4.z; As[akv + 3][r] = a4.w;
        }
        *reinterpret_cast<float4*>(&Bs[bk][bn4]) =
            *reinterpret_cast<const float4*>(&G[(k0 + bk) * 64 + bn4]);
        __syncthreads();
#pragma unroll
        for (int kk = 0; kk < 16; kk++) {
            float ra[8], rb[4];
#pragma unroll
            for (int i = 0; i < 8; i++) ra[i] = As[kk][ty * 8 + i];
#pragma unroll
            for (int j = 0; j < 4; j++) rb[j] = Bs[kk][tx * 4 + j];
#pragma unroll
            for (int i = 0; i < 8; i++)
#pragma unroll
                for (int j = 0; j < 4; j++) acc[i][j] = fmaf(ra[i], rb[j], acc[i][j]);
        }
        __syncthreads();
    }
#pragma unroll
    for (int i = 0; i < 8; i++) {
        int r = bm + ty * 8 + i;
        float mv = g_maskf[b * NSEQ + r];
        size_t o = ((size_t)b * NSEQ + r) * DIMX + h * 64 + tx * 4;
        __nv_bfloat16 hh0, ll0, hh1, ll1, hh2, ll2, hh3, ll3;
        split_hl(acc[i][0] * mv, hh0, ll0);
        split_hl(acc[i][1] * mv, hh1, ll1);
        split_hl(acc[i][2] * mv, hh2, ll2);
        split_hl(acc[i][3] * mv, hh3, ll3);
        reinterpret_cast<__nv_bfloat162*>(&g_midh[o])[0] = __nv_bfloat162(hh0, hh1);
        reinterpret_cast<__nv_bfloat162*>(&g_midh[o])[1] = __nv_bfloat162(hh2, hh3);
        reinterpret_cast<__nv_bfloat162*>(&g_midl[o])[0] = __nv_bfloat162(ll0, ll1);
        reinterpret_cast<__nv_bfloat162*>(&g_midl[o])[1] = __nv_bfloat162(ll2, ll3);
    }
}

// ---------------- launcher ----------------
extern "C" void kernel_launch(void* const* d_in, const int* in_sizes, int n_in,
                              void* d_out, int out_size) {
    const float* x     = (const float*)d_in[0];
    const void*  mask  = d_in[1];
    const float* Wqkv  = (const float*)d_in[2];
    const float* agent = (const float*)d_in[3];
    const float* Wqa   = (const float*)d_in[4];
    const float* Wak   = (const float*)d_in[5];
    const float* Wout  = (const float*)d_in[6];
    float* out = (float*)d_out;
    (void)in_sizes; (void)n_in; (void)out_size;

    cudaFuncSetAttribute(gemm_mma_kernel<0>, cudaFuncAttributeMaxDynamicSharedMemorySize, GT_SMEM);
    cudaFuncSetAttribute(gemm_mma_kernel<1>, cudaFuncAttributeMaxDynamicSharedMemorySize, GT_SMEM);
    cudaFuncSetAttribute(qa_sim_softmax_kernel, cudaFuncAttributeMaxDynamicSharedMemorySize, SIM_SMEM);
    cudaFuncSetAttribute(ak_sim_kernel, cudaFuncAttributeMaxDynamicSharedMemorySize, SIM_SMEM);

    __nv_bfloat16 *xh, *xl, *wqh, *wql, *woh, *wol, *mh, *ml;
    cudaGetSymbolAddress((void**)&xh,  g_xh);
    cudaGetSymbolAddress((void**)&xl,  g_xl);
    cudaGetSymbolAddress((void**)&wqh, g_wqkvh);
    cudaGetSymbolAddress((void**)&wql, g_wqkvl);
    cudaGetSymbolAddress((void**)&woh, g_wouth);
    cudaGetSymbolAddress((void**)&wol, g_woutl);
    cudaGetSymbolAddress((void**)&mh,  g_midh);
    cudaGetSymbolAddress((void**)&ml,  g_midl);

    mask_expand_kernel<<<1, 1024>>>(mask);
    conv_split_kernel<<<(NB * NSEQ * DIMX / 4 + 255) / 256, 256>>>(x, xh, xl, NB * NSEQ * DIMX / 4);
    conv_wt_kernel<<<dim3(96, 32), 256>>>(Wqkv, wqh, wql, 1024, 3072);
    conv_wt_kernel<<<dim3(32, 32), 256>>>(Wout, woh, wol, 1024, 1024);

    gemm_mma_kernel<1><<<dim3(24, 128), 256, GT_SMEM>>>(xh, xl, wqh, wql, nullptr, 1024, 3072);

    qa_sim_softmax_kernel<<<dim3(32, 64), 256, SIM_SMEM>>>(agent);  // sim + softmax fused
    ak_sim_kernel<<<dim3(32, 64), 256, SIM_SMEM>>>(agent);
    ak_stats_kernel<<<BHN * MAG, 256>>>();
    mix_heads_kernel<<<8192, 256>>>(Wqa);                            // qa head mix
    mix_ak_exp_kernel<<<8192, 256>>>(Wak);                           // ak softmax + mix fused
    agent_out_kernel<<<dim3(8, 64), 256>>>();
    reduce_agent_kernel<<<(BHN * MAG * DHEAD) / 256, 256>>>();
    out_mid_kernel<<<dim3(32, 64), 256>>>();

    gemm_mma_kernel<0><<<dim3(8, 128), 256, GT_SMEM>>>(mh, ml, woh, wol, out, 1024, 1024);
}